// round 3
// baseline (speedup 1.0000x reference)
#include <cuda_runtime.h>
#include <cuda_bf16.h>

// Problem shapes (fixed by the dataset):
//   joint_feature        [B=1024, D=1024]  f32
//   confounder_dictionary[K=256,  D=1024]  f32
//   prior                [K=256,  1]       f32
//   Wq                   [D=1024, P=768]   f32
//   Wk                   [D=1024, P=768]   f32
//   out                  [B=1024, D=1024]  f32
//
// Restructured dataflow (numerically fp32 throughout):
//   Kmat  = conf @ Wk                  [K, P]
//   W2    = Wq @ Kmat^T                [D, K]
//   S     = (joint @ W2) * (1/32)      [B, K]
//   A     = softmax_rows(S)            [B, K]
//   out   = joint + A @ (conf * prior) [B, D]

#define BB 1024
#define KK 256
#define DD 1024
#define PP 768

__device__ __align__(16) float gKmat[KK * PP];     // 768 KB
__device__ __align__(16) float gW2[DD * KK];       // 1 MB
__device__ __align__(16) float gS[BB * KK];        // 1 MB

// ---------------------------------------------------------------------------
// Generic 64x64x16 tiled SGEMM, NN:  C[M,N] = alpha * A[M,K] @ B[K,N]
// 256 threads, 4x4 accum per thread. Requires M%64==0, N%64==0, K%16==0.
// ---------------------------------------------------------------------------
__global__ __launch_bounds__(256) void sgemm_nn(
    const float* __restrict__ A, const float* __restrict__ Bm,
    float* __restrict__ C, int M, int N, int K, float alpha)
{
    __shared__ float As[16][64];
    __shared__ float Bs[16][64];
    const int tid = threadIdx.x;
    const int tx = tid & 15, ty = tid >> 4;
    const int row0 = blockIdx.y * 64, col0 = blockIdx.x * 64;

    const int a_m = tid >> 2;          // 0..63
    const int a_k = (tid & 3) * 4;     // 0,4,8,12
    const int b_k = tid >> 4;          // 0..15
    const int b_n = (tid & 15) * 4;    // 0..60

    float acc[4][4] = {};

    for (int k0 = 0; k0 < K; k0 += 16) {
        float4 av = *(const float4*)&A[(size_t)(row0 + a_m) * K + k0 + a_k];
        As[a_k + 0][a_m] = av.x;
        As[a_k + 1][a_m] = av.y;
        As[a_k + 2][a_m] = av.z;
        As[a_k + 3][a_m] = av.w;
        float4 bv = *(const float4*)&Bm[(size_t)(k0 + b_k) * N + col0 + b_n];
        *(float4*)&Bs[b_k][b_n] = bv;
        __syncthreads();

        #pragma unroll
        for (int kk = 0; kk < 16; kk++) {
            float4 a4 = *(const float4*)&As[kk][ty * 4];
            float4 b4 = *(const float4*)&Bs[kk][tx * 4];
            float avr[4] = {a4.x, a4.y, a4.z, a4.w};
            float bvr[4] = {b4.x, b4.y, b4.z, b4.w};
            #pragma unroll
            for (int i = 0; i < 4; i++)
                #pragma unroll
                for (int j = 0; j < 4; j++)
                    acc[i][j] = fmaf(avr[i], bvr[j], acc[i][j]);
        }
        __syncthreads();
    }

    #pragma unroll
    for (int i = 0; i < 4; i++) {
        float4 o;
        o.x = alpha * acc[i][0];
        o.y = alpha * acc[i][1];
        o.z = alpha * acc[i][2];
        o.w = alpha * acc[i][3];
        *(float4*)&C[(size_t)(row0 + ty * 4 + i) * N + col0 + tx * 4] = o;
    }
}

// ---------------------------------------------------------------------------
// NT SGEMM:  C[M,N] = A[M,K] @ B[N,K]^T   (both operands K-major row-major)
// ---------------------------------------------------------------------------
__global__ __launch_bounds__(256) void sgemm_nt(
    const float* __restrict__ A, const float* __restrict__ Bm,
    float* __restrict__ C, int M, int N, int K)
{
    __shared__ float As[16][64];
    __shared__ float Bs[16][64];
    const int tid = threadIdx.x;
    const int tx = tid & 15, ty = tid >> 4;
    const int row0 = blockIdx.y * 64, col0 = blockIdx.x * 64;

    const int a_m = tid >> 2;
    const int a_k = (tid & 3) * 4;

    float acc[4][4] = {};

    for (int k0 = 0; k0 < K; k0 += 16) {
        float4 av = *(const float4*)&A[(size_t)(row0 + a_m) * K + k0 + a_k];
        As[a_k + 0][a_m] = av.x;
        As[a_k + 1][a_m] = av.y;
        As[a_k + 2][a_m] = av.z;
        As[a_k + 3][a_m] = av.w;
        float4 bv = *(const float4*)&Bm[(size_t)(col0 + a_m) * K + k0 + a_k];
        Bs[a_k + 0][a_m] = bv.x;
        Bs[a_k + 1][a_m] = bv.y;
        Bs[a_k + 2][a_m] = bv.z;
        Bs[a_k + 3][a_m] = bv.w;
        __syncthreads();

        #pragma unroll
        for (int kk = 0; kk < 16; kk++) {
            float4 a4 = *(const float4*)&As[kk][ty * 4];
            float4 b4 = *(const float4*)&Bs[kk][tx * 4];
            float avr[4] = {a4.x, a4.y, a4.z, a4.w};
            float bvr[4] = {b4.x, b4.y, b4.z, b4.w};
            #pragma unroll
            for (int i = 0; i < 4; i++)
                #pragma unroll
                for (int j = 0; j < 4; j++)
                    acc[i][j] = fmaf(avr[i], bvr[j], acc[i][j]);
        }
        __syncthreads();
    }

    #pragma unroll
    for (int i = 0; i < 4; i++) {
        float4 o = {acc[i][0], acc[i][1], acc[i][2], acc[i][3]};
        *(float4*)&C[(size_t)(row0 + ty * 4 + i) * N + col0 + tx * 4] = o;
    }
}

// ---------------------------------------------------------------------------
// Row softmax, K=256 columns. One block per row, 256 threads.
// ---------------------------------------------------------------------------
__global__ __launch_bounds__(256) void softmax_rows(float* __restrict__ S)
{
    __shared__ float red[256];
    const int row = blockIdx.x;
    const int t = threadIdx.x;
    float x = S[row * KK + t];

    red[t] = x;
    __syncthreads();
    #pragma unroll
    for (int s = 128; s > 0; s >>= 1) {
        if (t < s) red[t] = fmaxf(red[t], red[t + s]);
        __syncthreads();
    }
    float mx = red[0];
    __syncthreads();

    float e = __expf(x - mx);
    red[t] = e;
    __syncthreads();
    #pragma unroll
    for (int s = 128; s > 0; s >>= 1) {
        if (t < s) red[t] += red[t + s];
        __syncthreads();
    }
    float inv = 1.0f / red[0];
    S[row * KK + t] = e * inv;
}

// ---------------------------------------------------------------------------
// Output GEMM with fused prior-scaling and residual add:
//   out[M,N] = attn[M,K] @ (conf[K,N] * prior[k]) + joint[M,N]
// ---------------------------------------------------------------------------
__global__ __launch_bounds__(256) void sgemm_out(
    const float* __restrict__ A, const float* __restrict__ Bm,
    const float* __restrict__ prior, const float* __restrict__ joint,
    float* __restrict__ C, int M, int N, int K)
{
    __shared__ float As[16][64];
    __shared__ float Bs[16][64];
    const int tid = threadIdx.x;
    const int tx = tid & 15, ty = tid >> 4;
    const int row0 = blockIdx.y * 64, col0 = blockIdx.x * 64;

    const int a_m = tid >> 2;
    const int a_k = (tid & 3) * 4;
    const int b_k = tid >> 4;
    const int b_n = (tid & 15) * 4;

    float acc[4][4] = {};

    for (int k0 = 0; k0 < K; k0 += 16) {
        float4 av = *(const float4*)&A[(size_t)(row0 + a_m) * K + k0 + a_k];
        As[a_k + 0][a_m] = av.x;
        As[a_k + 1][a_m] = av.y;
        As[a_k + 2][a_m] = av.z;
        As[a_k + 3][a_m] = av.w;
        float p = prior[k0 + b_k];
        float4 bv = *(const float4*)&Bm[(size_t)(k0 + b_k) * N + col0 + b_n];
        bv.x *= p; bv.y *= p; bv.z *= p; bv.w *= p;
        *(float4*)&Bs[b_k][b_n] = bv;
        __syncthreads();

        #pragma unroll
        for (int kk = 0; kk < 16; kk++) {
            float4 a4 = *(const float4*)&As[kk][ty * 4];
            float4 b4 = *(const float4*)&Bs[kk][tx * 4];
            float avr[4] = {a4.x, a4.y, a4.z, a4.w};
            float bvr[4] = {b4.x, b4.y, b4.z, b4.w};
            #pragma unroll
            for (int i = 0; i < 4; i++)
                #pragma unroll
                for (int j = 0; j < 4; j++)
                    acc[i][j] = fmaf(avr[i], bvr[j], acc[i][j]);
        }
        __syncthreads();
    }

    #pragma unroll
    for (int i = 0; i < 4; i++) {
        const size_t off = (size_t)(row0 + ty * 4 + i) * N + col0 + tx * 4;
        float4 jv = *(const float4*)&joint[off];
        float4 o;
        o.x = acc[i][0] + jv.x;
        o.y = acc[i][1] + jv.y;
        o.z = acc[i][2] + jv.z;
        o.w = acc[i][3] + jv.w;
        *(float4*)&C[off] = o;
    }
}

extern "C" void kernel_launch(void* const* d_in, const int* in_sizes, int n_in,
                              void* d_out, int out_size)
{
    const float* joint = (const float*)d_in[0];   // [B, D]
    const float* conf  = (const float*)d_in[1];   // [K, D]
    const float* prior = (const float*)d_in[2];   // [K, 1]
    const float* Wq    = (const float*)d_in[3];   // [D, P]
    const float* Wk    = (const float*)d_in[4];   // [D, P]
    float* out = (float*)d_out;                   // [B, D]

    float* kmat; cudaGetSymbolAddress((void**)&kmat, gKmat);
    float* w2;   cudaGetSymbolAddress((void**)&w2,   gW2);
    float* sbuf; cudaGetSymbolAddress((void**)&sbuf, gS);

    // 1) Kmat[K,P] = conf[K,D] @ Wk[D,P]
    {
        dim3 grid(PP / 64, KK / 64);
        sgemm_nn<<<grid, 256>>>(conf, Wk, kmat, KK, PP, DD, 1.0f);
    }
    // 2) W2[D,K] = Wq[D,P] @ Kmat[K,P]^T
    {
        dim3 grid(KK / 64, DD / 64);
        sgemm_nt<<<grid, 256>>>(Wq, kmat, w2, DD, KK, PP);
    }
    // 3) S[B,K] = (joint[B,D] @ W2[D,K]) / sqrt(1024)
    {
        dim3 grid(KK / 64, BB / 64);
        sgemm_nn<<<grid, 256>>>(joint, w2, sbuf, BB, KK, DD, 0.03125f);
    }
    // 4) softmax rows of S
    softmax_rows<<<BB, 256>>>(sbuf);
    // 5) out = S @ (conf * prior) + joint
    {
        dim3 grid(DD / 64, BB / 64);
        sgemm_out<<<grid, 256>>>(sbuf, conf, prior, joint, out, BB, DD, KK);
    }
}

// round 6
// speedup vs baseline: 3.1615x; 3.1615x over previous
#include <cuda_runtime.h>
#include <cuda_bf16.h>
#include <cstdint>

// Shapes (fixed): joint [B=1024, D=1024], conf [K=256, D=1024], prior [K,1],
// Wq [D, P=768], Wk [D, P=768], out [B, D]. All fp32 in global.
//
// Dataflow (bf16 mma.sync HMMA GEMMs, fp32 accumulate, all NT: C = A @ B^T):
//   conv:     joint_bf, conf_bf, Wq_bf    (fp32 -> bf16)
//   transp:   WkT_bf[P,D]   = Wk^T
//             confTp_bf[D,K]= (conf*prior)^T
//   G1: Kmat[256,768]  = conf_bf  @ WkT_bf^T      (K=1024) -> bf16
//   G2: W2T [256,1024] = Kmat     @ Wq_bf^T       (K=768)  -> bf16
//   G3: S   [1024,256] = joint_bf @ W2T^T * 1/32  (K=1024) -> f32
//   softmax rows of S -> attn_bf [1024,256]
//   G4: out [1024,1024]= attn_bf  @ confTp^T + joint (K=256) -> f32

#define BB 1024
#define KK 256
#define DD 1024
#define PP 768

// ---------------- scratch (device globals; no allocation allowed) ----------
__device__ __align__(16) __nv_bfloat16 g_joint_bf[BB * DD];
__device__ __align__(16) __nv_bfloat16 g_conf_bf[KK * DD];
__device__ __align__(16) __nv_bfloat16 g_Wq_bf[DD * PP];
__device__ __align__(16) __nv_bfloat16 g_WkT_bf[PP * DD];
__device__ __align__(16) __nv_bfloat16 g_confTp_bf[DD * KK];
__device__ __align__(16) __nv_bfloat16 g_Kmat_bf[KK * PP];
__device__ __align__(16) __nv_bfloat16 g_W2T_bf[KK * DD];
__device__ __align__(16) float         g_S[BB * KK];
__device__ __align__(16) __nv_bfloat16 g_attn_bf[BB * KK];

// ---------------- baseline-PTX helpers (no arch-gated instructions) --------
__device__ __forceinline__ uint32_t smem_u32(const void* p) {
    uint32_t a;
    asm("{ .reg .u64 t; cvta.to.shared.u64 t, %1; cvt.u32.u64 %0, t; }"
        : "=r"(a) : "l"(p));
    return a;
}
__device__ __forceinline__ void cp_async16(uint32_t dst, const void* src) {
    asm volatile("cp.async.cg.shared.global [%0], [%1], 16;"
                 :: "r"(dst), "l"(src) : "memory");
}
__device__ __forceinline__ void cp_commit() {
    asm volatile("cp.async.commit_group;" ::: "memory");
}
__device__ __forceinline__ void cp_wait1() {
    asm volatile("cp.async.wait_group 1;" ::: "memory");
}
__device__ __forceinline__ void cp_wait0() {
    asm volatile("cp.async.wait_group 0;" ::: "memory");
}
__device__ __forceinline__ void ldmatrix_x4(uint32_t* r, uint32_t addr) {
    asm volatile("ldmatrix.sync.aligned.m8n8.x4.shared.b16 {%0,%1,%2,%3}, [%4];"
                 : "=r"(r[0]), "=r"(r[1]), "=r"(r[2]), "=r"(r[3]) : "r"(addr));
}
__device__ __forceinline__ void mma_bf16(float* c, const uint32_t* a,
                                         uint32_t b0, uint32_t b1) {
    asm volatile(
        "mma.sync.aligned.m16n8k16.row.col.f32.bf16.bf16.f32 "
        "{%0,%1,%2,%3}, {%4,%5,%6,%7}, {%8,%9}, {%0,%1,%2,%3};"
        : "+f"(c[0]), "+f"(c[1]), "+f"(c[2]), "+f"(c[3])
        : "r"(a[0]), "r"(a[1]), "r"(a[2]), "r"(a[3]), "r"(b0), "r"(b1));
}
__device__ __forceinline__ uint32_t sw128(uint32_t off) {
    return off ^ ((off >> 3) & 0x70);
}

// ---------------- conversion / transpose kernels ----------------------------
__global__ __launch_bounds__(256) void conv_bf16(
    const float* __restrict__ in, __nv_bfloat16* __restrict__ out, int n4)
{
    int i = blockIdx.x * blockDim.x + threadIdx.x;
    if (i < n4) {
        float4 v = ((const float4*)in)[i];
        __nv_bfloat162 a = __floats2bfloat162_rn(v.x, v.y);
        __nv_bfloat162 b = __floats2bfloat162_rn(v.z, v.w);
        uint2 u;
        u.x = *reinterpret_cast<uint32_t*>(&a);
        u.y = *reinterpret_cast<uint32_t*>(&b);
        ((uint2*)out)[i] = u;
    }
}

// in [R,C] f32 -> out [C,R] bf16, optional per-input-row scale (prior).
__global__ __launch_bounds__(256) void transpose_bf16(
    const float* __restrict__ in, const float* __restrict__ scale,
    __nv_bfloat16* __restrict__ out, int R, int C)
{
    __shared__ float tile[32][33];
    int c0 = blockIdx.x * 32, r0 = blockIdx.y * 32;
    int tx = threadIdx.x, ty = threadIdx.y;   // 32 x 8
    #pragma unroll
    for (int i = 0; i < 32; i += 8) {
        int r = r0 + ty + i;
        float v = in[(size_t)r * C + c0 + tx];
        if (scale) v *= scale[r];
        tile[ty + i][tx] = v;
    }
    __syncthreads();
    #pragma unroll
    for (int i = 0; i < 32; i += 8)
        out[(size_t)(c0 + ty + i) * R + r0 + tx] = __float2bfloat16(tile[tx][ty + i]);
}

// ---------------- softmax (warp per row), fp32 in -> bf16 out ---------------
__global__ __launch_bounds__(256) void softmax_bf16(
    const float* __restrict__ S, __nv_bfloat16* __restrict__ A)
{
    int w = threadIdx.x >> 5, lid = threadIdx.x & 31;
    int row = blockIdx.x * 8 + w;
    const float4* p = (const float4*)(S + (size_t)row * KK);
    float4 v0 = p[lid], v1 = p[lid + 32];
    float e[8] = {v0.x, v0.y, v0.z, v0.w, v1.x, v1.y, v1.z, v1.w};
    float mx = e[0];
    #pragma unroll
    for (int i = 1; i < 8; i++) mx = fmaxf(mx, e[i]);
    #pragma unroll
    for (int o = 16; o; o >>= 1) mx = fmaxf(mx, __shfl_xor_sync(~0u, mx, o));
    float s = 0.f;
    #pragma unroll
    for (int i = 0; i < 8; i++) { e[i] = __expf(e[i] - mx); s += e[i]; }
    #pragma unroll
    for (int o = 16; o; o >>= 1) s += __shfl_xor_sync(~0u, s, o);
    float inv = 1.0f / s;
    __nv_bfloat162 b01 = __floats2bfloat162_rn(e[0] * inv, e[1] * inv);
    __nv_bfloat162 b23 = __floats2bfloat162_rn(e[2] * inv, e[3] * inv);
    __nv_bfloat162 b45 = __floats2bfloat162_rn(e[4] * inv, e[5] * inv);
    __nv_bfloat162 b67 = __floats2bfloat162_rn(e[6] * inv, e[7] * inv);
    uint2 lo = make_uint2(*reinterpret_cast<uint32_t*>(&b01), *reinterpret_cast<uint32_t*>(&b23));
    uint2 hi = make_uint2(*reinterpret_cast<uint32_t*>(&b45), *reinterpret_cast<uint32_t*>(&b67));
    *(uint2*)(A + (size_t)row * KK + lid * 4)       = lo;
    *(uint2*)(A + (size_t)row * KK + 128 + lid * 4) = hi;
}

// ---------------- HMMA NT GEMM: C[M,N] = A[M,K] @ B[N,K]^T ------------------
// bf16 K-major operands, fp32 accum. CTA tile 64x64, 4 warps (2x2, each 32x32),
// BK=64 (128B rows, SW128 swizzle), cp.async double buffer.
// mode: 0 = bf16 out, 1 = f32 out * alpha, 2 = f32 out + resid.
#define TM 64
#define TN 64
#define TKB 128                        // bytes per smem row (64 bf16)
#define A_BYTES (TM * TKB)             // 8 KB
#define STAGE_BYTES (2 * A_BYTES)      // 16 KB (A then B)

__global__ __launch_bounds__(128) void gemm_nt_hmma(
    const __nv_bfloat16* __restrict__ A, const __nv_bfloat16* __restrict__ B,
    void* __restrict__ Cout, const float* __restrict__ resid,
    int Ntot, int K, float alpha, int mode)
{
    extern __shared__ char dsm_raw[];
    char* dsm = (char*)(((uintptr_t)dsm_raw + 1023) & ~(uintptr_t)1023);
    const uint32_t smem_base = smem_u32(dsm);

    const int tid = threadIdx.x;
    const int wid = tid >> 5;
    const int lid = tid & 31;
    const int wm = (wid >> 1) * 32;     // warp row offset in tile
    const int wn = (wid & 1) * 32;      // warp col offset in tile

    const int row0 = blockIdx.y * TM;
    const int col0 = blockIdx.x * TN;
    const int nk = K >> 6;

    const char* Abase = (const char*)A;
    const char* Bbase = (const char*)B;

    float acc[2][4][4] = {};

    // async load of stage s for k-iter it (A tile + B tile, 4 chunks each/thread)
    auto load_stage = [&](int s, int it) {
        const uint32_t sA = smem_base + s * STAGE_BYTES;
        const uint32_t sB = sA + A_BYTES;
        #pragma unroll
        for (int i = 0; i < 4; i++) {
            int ci = tid + i * 128;           // 0..511
            int r = ci >> 3, c16 = ci & 7;
            size_t gb = ((size_t)(row0 + r) * K + it * 64) * 2 + c16 * 16;
            uint32_t off = r * TKB + c16 * 16;
            cp_async16(sA + sw128(off), Abase + gb);
        }
        #pragma unroll
        for (int i = 0; i < 4; i++) {
            int ci = tid + i * 128;
            int r = ci >> 3, c16 = ci & 7;
            size_t gb = ((size_t)(col0 + r) * K + it * 64) * 2 + c16 * 16;
            uint32_t off = r * TKB + c16 * 16;
            cp_async16(sB + sw128(off), Bbase + gb);
        }
        cp_commit();
    };

    load_stage(0, 0);

    for (int it = 0; it < nk; ++it) {
        if (it + 1 < nk) { load_stage((it + 1) & 1, it + 1); cp_wait1(); }
        else             { cp_wait0(); }
        __syncthreads();

        const uint32_t sA = smem_base + (it & 1) * STAGE_BYTES;
        const uint32_t sB = sA + A_BYTES;

        #pragma unroll
        for (int ks = 0; ks < 4; ++ks) {
            uint32_t afr[2][4], bfr[2][4];
            #pragma unroll
            for (int mi = 0; mi < 2; ++mi) {
                int row = wm + mi * 16 + (lid & 15);
                uint32_t off = row * TKB + ks * 32 + (lid >> 4) * 16;
                ldmatrix_x4(afr[mi], sA + sw128(off));
            }
            #pragma unroll
            for (int np = 0; np < 2; ++np) {
                int row = wn + np * 16 + ((lid >> 4) << 3) + (lid & 7);
                uint32_t off = row * TKB + ks * 32 + ((lid >> 3) & 1) * 16;
                ldmatrix_x4(bfr[np], sB + sw128(off));
            }
            #pragma unroll
            for (int mi = 0; mi < 2; ++mi)
                #pragma unroll
                for (int ni = 0; ni < 4; ++ni)
                    mma_bf16(acc[mi][ni], afr[mi],
                             bfr[ni >> 1][(ni & 1) * 2],
                             bfr[ni >> 1][(ni & 1) * 2 + 1]);
        }
        __syncthreads();
    }

    // Epilogue: thread (group, tc): rows m+group / m+group+8, cols n+tc, n+tc+1
    const int group = lid >> 2;
    const int tc = (lid & 3) * 2;
    #pragma unroll
    for (int mi = 0; mi < 2; ++mi) {
        #pragma unroll
        for (int ni = 0; ni < 4; ++ni) {
            int r = row0 + wm + mi * 16 + group;
            int c = col0 + wn + ni * 8 + tc;
            float* cc = acc[mi][ni];
            if (mode == 0) {
                __nv_bfloat16* o = (__nv_bfloat16*)Cout;
                __nv_bfloat162 p0 = __floats2bfloat162_rn(cc[0], cc[1]);
                __nv_bfloat162 p1 = __floats2bfloat162_rn(cc[2], cc[3]);
                *(uint32_t*)(o + (size_t)r * Ntot + c) = *reinterpret_cast<uint32_t*>(&p0);
                *(uint32_t*)(o + (size_t)(r + 8) * Ntot + c) = *reinterpret_cast<uint32_t*>(&p1);
            } else if (mode == 1) {
                float* o = (float*)Cout;
                *(float2*)(o + (size_t)r * Ntot + c) = make_float2(alpha * cc[0], alpha * cc[1]);
                *(float2*)(o + (size_t)(r + 8) * Ntot + c) = make_float2(alpha * cc[2], alpha * cc[3]);
            } else {
                float* o = (float*)Cout;
                float2 j0 = *(const float2*)(resid + (size_t)r * Ntot + c);
                float2 j1 = *(const float2*)(resid + (size_t)(r + 8) * Ntot + c);
                *(float2*)(o + (size_t)r * Ntot + c) = make_float2(cc[0] + j0.x, cc[1] + j0.y);
                *(float2*)(o + (size_t)(r + 8) * Ntot + c) = make_float2(cc[2] + j1.x, cc[3] + j1.y);
            }
        }
    }
}

// ---------------- host ------------------------------------------------------
extern "C" void kernel_launch(void* const* d_in, const int* in_sizes, int n_in,
                              void* d_out, int out_size)
{
    const float* joint = (const float*)d_in[0];   // [B, D]
    const float* conf  = (const float*)d_in[1];   // [K, D]
    const float* prior = (const float*)d_in[2];   // [K, 1]
    const float* Wq    = (const float*)d_in[3];   // [D, P]
    const float* Wk    = (const float*)d_in[4];   // [D, P]
    float* out = (float*)d_out;                   // [B, D]

    __nv_bfloat16 *joint_bf, *conf_bf, *Wq_bf, *WkT_bf, *confTp_bf, *Kmat_bf, *W2T_bf, *attn_bf;
    float* Sbuf;
    cudaGetSymbolAddress((void**)&joint_bf,  g_joint_bf);
    cudaGetSymbolAddress((void**)&conf_bf,   g_conf_bf);
    cudaGetSymbolAddress((void**)&Wq_bf,     g_Wq_bf);
    cudaGetSymbolAddress((void**)&WkT_bf,    g_WkT_bf);
    cudaGetSymbolAddress((void**)&confTp_bf, g_confTp_bf);
    cudaGetSymbolAddress((void**)&Kmat_bf,   g_Kmat_bf);
    cudaGetSymbolAddress((void**)&W2T_bf,    g_W2T_bf);
    cudaGetSymbolAddress((void**)&Sbuf,      g_S);
    cudaGetSymbolAddress((void**)&attn_bf,   g_attn_bf);

    const int smem_bytes = 2 * STAGE_BYTES + 1024;   // 33 KB
    cudaFuncSetAttribute(gemm_nt_hmma, cudaFuncAttributeMaxDynamicSharedMemorySize, smem_bytes);

    // conversions
    conv_bf16<<<(BB * DD / 4 + 255) / 256, 256>>>(joint, joint_bf, BB * DD / 4);
    conv_bf16<<<(KK * DD / 4 + 255) / 256, 256>>>(conf, conf_bf, KK * DD / 4);
    conv_bf16<<<(DD * PP / 4 + 255) / 256, 256>>>(Wq, Wq_bf, DD * PP / 4);
    {   // WkT[P, D] = Wk^T
        dim3 g(PP / 32, DD / 32), b(32, 8);
        transpose_bf16<<<g, b>>>(Wk, nullptr, WkT_bf, DD, PP);
    }
    {   // confTp[D, K] = (conf * prior)^T
        dim3 g(DD / 32, KK / 32), b(32, 8);
        transpose_bf16<<<g, b>>>(conf, prior, confTp_bf, KK, DD);
    }
    // G1: Kmat[256, 768] = conf_bf @ WkT^T  (K = 1024)
    {
        dim3 g(PP / TN, KK / TM);
        gemm_nt_hmma<<<g, 128, smem_bytes>>>(conf_bf, WkT_bf, Kmat_bf, nullptr,
                                             PP, DD, 1.0f, 0);
    }
    // G2: W2T[256, 1024] = Kmat @ Wq_bf^T  (K = 768)
    {
        dim3 g(DD / TN, KK / TM);
        gemm_nt_hmma<<<g, 128, smem_bytes>>>(Kmat_bf, Wq_bf, W2T_bf, nullptr,
                                             DD, PP, 1.0f, 0);
    }
    // G3: S[1024, 256] = joint_bf @ W2T^T * (1/32)  (K = 1024), fp32 out
    {
        dim3 g(KK / TN, BB / TM);
        gemm_nt_hmma<<<g, 128, smem_bytes>>>(joint_bf, W2T_bf, Sbuf, nullptr,
                                             KK, DD, 0.03125f, 1);
    }
    // softmax rows -> attn bf16
    softmax_bf16<<<BB / 8, 256>>>(Sbuf, attn_bf);
    // G4: out[1024, 1024] = attn_bf @ confTp^T + joint  (K = 256)
    {
        dim3 g(DD / TN, BB / TM);
        gemm_nt_hmma<<<g, 128, smem_bytes>>>(attn_bf, confTp_bf, out, joint,
                                             DD, KK, 1.0f, 2);
    }
}

// round 7
// speedup vs baseline: 5.2392x; 1.6572x over previous
#include <cuda_runtime.h>
#include <cuda_bf16.h>
#include <cstdint>

// Shapes (fixed): joint [B=1024, D=1024], conf [K=256, D=1024], prior [K,1],
// Wq [D, P=768], Wk [D, P=768], out [B, D]. All fp32 in global.
//
// Dataflow (bf16 mma.sync HMMA, fp32 accum). NT = B K-major, NN = B N-major
// (loaded with ldmatrix.trans — no explicit transposes anywhere):
//   conv:  joint_bf, conf_bf, Wq_bf, Wk_bf   (one fused kernel)
//   G1(NN): Kmat[256,768]  = conf_bf  @ Wk_bf          (K=1024) -> bf16
//   G2(NT): W2T [256,1024] = Kmat     @ Wq_bf^T        (K=768)  -> bf16
//   G3(NT): S   [1024,256] = joint_bf @ W2T^T * 1/32   (K=1024) -> f32
//   softmax rows of S, scaled by prior -> attn_bf [1024,256]
//   G4(NN): out [1024,1024]= attn_bf  @ conf_bf + joint (K=256) -> f32

#define BB 1024
#define KK 256
#define DD 1024
#define PP 768

// ---------------- scratch (device globals; no allocation allowed) ----------
__device__ __align__(16) __nv_bfloat16 g_joint_bf[BB * DD];
__device__ __align__(16) __nv_bfloat16 g_conf_bf[KK * DD];
__device__ __align__(16) __nv_bfloat16 g_Wq_bf[DD * PP];
__device__ __align__(16) __nv_bfloat16 g_Wk_bf[DD * PP];
__device__ __align__(16) __nv_bfloat16 g_Kmat_bf[KK * PP];
__device__ __align__(16) __nv_bfloat16 g_W2T_bf[KK * DD];
__device__ __align__(16) float         g_S[BB * KK];
__device__ __align__(16) __nv_bfloat16 g_attn_bf[BB * KK];

// ---------------- baseline-PTX helpers (no arch-gated instructions) --------
__device__ __forceinline__ uint32_t smem_u32(const void* p) {
    uint32_t a;
    asm("{ .reg .u64 t; cvta.to.shared.u64 t, %1; cvt.u32.u64 %0, t; }"
        : "=r"(a) : "l"(p));
    return a;
}
__device__ __forceinline__ void cp_async16(uint32_t dst, const void* src) {
    asm volatile("cp.async.cg.shared.global [%0], [%1], 16;"
                 :: "r"(dst), "l"(src) : "memory");
}
__device__ __forceinline__ void cp_commit() {
    asm volatile("cp.async.commit_group;" ::: "memory");
}
__device__ __forceinline__ void cp_wait1() {
    asm volatile("cp.async.wait_group 1;" ::: "memory");
}
__device__ __forceinline__ void cp_wait0() {
    asm volatile("cp.async.wait_group 0;" ::: "memory");
}
__device__ __forceinline__ void ldmatrix_x4(uint32_t* r, uint32_t addr) {
    asm volatile("ldmatrix.sync.aligned.m8n8.x4.shared.b16 {%0,%1,%2,%3}, [%4];"
                 : "=r"(r[0]), "=r"(r[1]), "=r"(r[2]), "=r"(r[3]) : "r"(addr));
}
__device__ __forceinline__ void ldmatrix_x4_trans(uint32_t* r, uint32_t addr) {
    asm volatile("ldmatrix.sync.aligned.m8n8.x4.trans.shared.b16 {%0,%1,%2,%3}, [%4];"
                 : "=r"(r[0]), "=r"(r[1]), "=r"(r[2]), "=r"(r[3]) : "r"(addr));
}
__device__ __forceinline__ void mma_bf16(float* c, const uint32_t* a,
                                         uint32_t b0, uint32_t b1) {
    asm volatile(
        "mma.sync.aligned.m16n8k16.row.col.f32.bf16.bf16.f32 "
        "{%0,%1,%2,%3}, {%4,%5,%6,%7}, {%8,%9}, {%0,%1,%2,%3};"
        : "+f"(c[0]), "+f"(c[1]), "+f"(c[2]), "+f"(c[3])
        : "r"(a[0]), "r"(a[1]), "r"(a[2]), "r"(a[3]), "r"(b0), "r"(b1));
}
__device__ __forceinline__ uint32_t sw128(uint32_t off) {
    return off ^ ((off >> 3) & 0x70);
}

// ---------------- fused fp32 -> bf16 conversion (all 4 inputs) --------------
#define N4_JOINT  (BB * DD / 4)                       // 262144
#define N4_CONF   (KK * DD / 4)                       //  65536
#define N4_W      (DD * PP / 4)                       // 196608
#define N4_TOTAL  (N4_JOINT + N4_CONF + 2 * N4_W)     // 720896

__global__ __launch_bounds__(256) void conv_all(
    const float* __restrict__ joint, const float* __restrict__ conf,
    const float* __restrict__ wq, const float* __restrict__ wk,
    __nv_bfloat16* __restrict__ jb, __nv_bfloat16* __restrict__ cb,
    __nv_bfloat16* __restrict__ qb, __nv_bfloat16* __restrict__ kb)
{
    int i = blockIdx.x * blockDim.x + threadIdx.x;
    const float* src;
    __nv_bfloat16* dst;
    int off;
    if (i < N4_JOINT)                       { src = joint; dst = jb; off = i; }
    else if (i < N4_JOINT + N4_CONF)        { src = conf;  dst = cb; off = i - N4_JOINT; }
    else if (i < N4_JOINT + N4_CONF + N4_W) { src = wq;    dst = qb; off = i - N4_JOINT - N4_CONF; }
    else if (i < N4_TOTAL)                  { src = wk;    dst = kb; off = i - N4_JOINT - N4_CONF - N4_W; }
    else return;
    float4 v = ((const float4*)src)[off];
    __nv_bfloat162 a = __floats2bfloat162_rn(v.x, v.y);
    __nv_bfloat162 b = __floats2bfloat162_rn(v.z, v.w);
    uint2 u;
    u.x = *reinterpret_cast<uint32_t*>(&a);
    u.y = *reinterpret_cast<uint32_t*>(&b);
    ((uint2*)dst)[off] = u;
}

// ------- softmax (warp per row), fp32 in -> bf16 out, fused *prior[k] -------
__global__ __launch_bounds__(256) void softmax_bf16(
    const float* __restrict__ S, const float* __restrict__ prior,
    __nv_bfloat16* __restrict__ A)
{
    int w = threadIdx.x >> 5, lid = threadIdx.x & 31;
    int row = blockIdx.x * 8 + w;
    const float4* p = (const float4*)(S + (size_t)row * KK);
    float4 v0 = p[lid], v1 = p[lid + 32];
    float e[8] = {v0.x, v0.y, v0.z, v0.w, v1.x, v1.y, v1.z, v1.w};
    float mx = e[0];
    #pragma unroll
    for (int i = 1; i < 8; i++) mx = fmaxf(mx, e[i]);
    #pragma unroll
    for (int o = 16; o; o >>= 1) mx = fmaxf(mx, __shfl_xor_sync(~0u, mx, o));
    float s = 0.f;
    #pragma unroll
    for (int i = 0; i < 8; i++) { e[i] = __expf(e[i] - mx); s += e[i]; }
    #pragma unroll
    for (int o = 16; o; o >>= 1) s += __shfl_xor_sync(~0u, s, o);
    float inv = 1.0f / s;
    float4 p0 = ((const float4*)prior)[lid];
    float4 p1 = ((const float4*)prior)[lid + 32];
    __nv_bfloat162 b01 = __floats2bfloat162_rn(e[0] * inv * p0.x, e[1] * inv * p0.y);
    __nv_bfloat162 b23 = __floats2bfloat162_rn(e[2] * inv * p0.z, e[3] * inv * p0.w);
    __nv_bfloat162 b45 = __floats2bfloat162_rn(e[4] * inv * p1.x, e[5] * inv * p1.y);
    __nv_bfloat162 b67 = __floats2bfloat162_rn(e[6] * inv * p1.z, e[7] * inv * p1.w);
    uint2 lo = make_uint2(*reinterpret_cast<uint32_t*>(&b01), *reinterpret_cast<uint32_t*>(&b23));
    uint2 hi = make_uint2(*reinterpret_cast<uint32_t*>(&b45), *reinterpret_cast<uint32_t*>(&b67));
    *(uint2*)(A + (size_t)row * KK + lid * 4)       = lo;
    *(uint2*)(A + (size_t)row * KK + 128 + lid * 4) = hi;
}

// ---------------- HMMA GEMM ------------------------------------------------
// BNN=0: C[M,N] = A[M,K] @ B[N,K]^T   (B K-major, ldmatrix non-trans)
// BNN=1: C[M,N] = A[M,K] @ B[K,N]     (B N-major, ldmatrix.trans)
// bf16 operands, fp32 accum. CTA tile 64x64, 4 warps (2x2, each 32x32),
// BK=64 (128B smem rows, SW128), cp.async double buffer.
// MODE: 0 = bf16 out, 1 = f32 out * alpha, 2 = f32 out + resid.
#define TM 64
#define TN 64
#define TKB 128
#define A_BYTES (TM * TKB)
#define STAGE_BYTES (2 * A_BYTES)

template <int BNN, int MODE>
__global__ __launch_bounds__(128) void gemm_hmma(
    const __nv_bfloat16* __restrict__ A, const __nv_bfloat16* __restrict__ B,
    void* __restrict__ Cout, const float* __restrict__ resid,
    int Ntot, int K, float alpha)
{
    extern __shared__ char dsm_raw[];
    char* dsm = (char*)(((uintptr_t)dsm_raw + 1023) & ~(uintptr_t)1023);
    const uint32_t smem_base = smem_u32(dsm);

    const int tid = threadIdx.x;
    const int wid = tid >> 5;
    const int lid = tid & 31;
    const int wm = (wid >> 1) * 32;
    const int wn = (wid & 1) * 32;

    const int row0 = blockIdx.y * TM;
    const int col0 = blockIdx.x * TN;
    const int nk = K >> 6;

    const char* Abase = (const char*)A;
    const char* Bbase = (const char*)B;

    float acc[2][4][4] = {};

    auto load_stage = [&](int s, int it) {
        const uint32_t sA = smem_base + s * STAGE_BYTES;
        const uint32_t sB = sA + A_BYTES;
        #pragma unroll
        for (int i = 0; i < 4; i++) {
            int ci = tid + i * 128;
            int r = ci >> 3, c16 = ci & 7;
            size_t gb = ((size_t)(row0 + r) * K + it * 64) * 2 + c16 * 16;
            uint32_t off = r * TKB + c16 * 16;
            cp_async16(sA + sw128(off), Abase + gb);
        }
        #pragma unroll
        for (int i = 0; i < 4; i++) {
            int ci = tid + i * 128;
            int r = ci >> 3, c16 = ci & 7;
            size_t gb;
            if (BNN) // B row-major [K, Ntot]; tile row r = k index it*64+r
                gb = ((size_t)(it * 64 + r) * Ntot + col0) * 2 + c16 * 16;
            else     // B row-major [N, K]; tile row r = n index col0+r
                gb = ((size_t)(col0 + r) * K + it * 64) * 2 + c16 * 16;
            uint32_t off = r * TKB + c16 * 16;
            cp_async16(sB + sw128(off), Bbase + gb);
        }
        cp_commit();
    };

    load_stage(0, 0);

    for (int it = 0; it < nk; ++it) {
        if (it + 1 < nk) { load_stage((it + 1) & 1, it + 1); cp_wait1(); }
        else             { cp_wait0(); }
        __syncthreads();

        const uint32_t sA = smem_base + (it & 1) * STAGE_BYTES;
        const uint32_t sB = sA + A_BYTES;

        #pragma unroll
        for (int ks = 0; ks < 4; ++ks) {
            uint32_t afr[2][4], bfr[2][4];
            #pragma unroll
            for (int mi = 0; mi < 2; ++mi) {
                int row = wm + mi * 16 + (lid & 15);
                uint32_t off = row * TKB + ks * 32 + (lid >> 4) * 16;
                ldmatrix_x4(afr[mi], sA + sw128(off));
            }
            #pragma unroll
            for (int np = 0; np < 2; ++np) {
                if (BNN) {
                    // tile is [k=64 rows][n=64 bf16]; 16x16 (k,n) chunk:
                    // m0:(k0-7,n0-7) m1:(k8-15,n0-7) m2:(k0-7,n8-15) m3:(k8-15,n8-15)
                    int k = ks * 16 + ((lid >> 3) & 1) * 8 + (lid & 7);
                    int n = wn + np * 16 + (lid >> 4) * 8;
                    uint32_t off = k * TKB + n * 2;
                    ldmatrix_x4_trans(bfr[np], sB + sw128(off));
                } else {
                    int row = wn + np * 16 + ((lid >> 4) << 3) + (lid & 7);
                    uint32_t off = row * TKB + ks * 32 + ((lid >> 3) & 1) * 16;
                    ldmatrix_x4(bfr[np], sB + sw128(off));
                }
            }
            #pragma unroll
            for (int mi = 0; mi < 2; ++mi)
                #pragma unroll
                for (int ni = 0; ni < 4; ++ni)
                    mma_bf16(acc[mi][ni], afr[mi],
                             bfr[ni >> 1][(ni & 1) * 2],
                             bfr[ni >> 1][(ni & 1) * 2 + 1]);
        }
        __syncthreads();
    }

    const int group = lid >> 2;
    const int tc = (lid & 3) * 2;
    #pragma unroll
    for (int mi = 0; mi < 2; ++mi) {
        #pragma unroll
        for (int ni = 0; ni < 4; ++ni) {
            int r = row0 + wm + mi * 16 + group;
            int c = col0 + wn + ni * 8 + tc;
            float* cc = acc[mi][ni];
            if (MODE == 0) {
                __nv_bfloat16* o = (__nv_bfloat16*)Cout;
                __nv_bfloat162 p0 = __floats2bfloat162_rn(cc[0], cc[1]);
                __nv_bfloat162 p1 = __floats2bfloat162_rn(cc[2], cc[3]);
                *(uint32_t*)(o + (size_t)r * Ntot + c) = *reinterpret_cast<uint32_t*>(&p0);
                *(uint32_t*)(o + (size_t)(r + 8) * Ntot + c) = *reinterpret_cast<uint32_t*>(&p1);
            } else if (MODE == 1) {
                float* o = (float*)Cout;
                *(float2*)(o + (size_t)r * Ntot + c) = make_float2(alpha * cc[0], alpha * cc[1]);
                *(float2*)(o + (size_t)(r + 8) * Ntot + c) = make_float2(alpha * cc[2], alpha * cc[3]);
            } else {
                float* o = (float*)Cout;
                float2 j0 = *(const float2*)(resid + (size_t)r * Ntot + c);
                float2 j1 = *(const float2*)(resid + (size_t)(r + 8) * Ntot + c);
                *(float2*)(o + (size_t)r * Ntot + c) = make_float2(cc[0] + j0.x, cc[1] + j0.y);
                *(float2*)(o + (size_t)(r + 8) * Ntot + c) = make_float2(cc[2] + j1.x, cc[3] + j1.y);
            }
        }
    }
}

// ---------------- host ------------------------------------------------------
extern "C" void kernel_launch(void* const* d_in, const int* in_sizes, int n_in,
                              void* d_out, int out_size)
{
    const float* joint = (const float*)d_in[0];
    const float* conf  = (const float*)d_in[1];
    const float* prior = (const float*)d_in[2];
    const float* Wq    = (const float*)d_in[3];
    const float* Wk    = (const float*)d_in[4];
    float* out = (float*)d_out;

    __nv_bfloat16 *joint_bf, *conf_bf, *Wq_bf, *Wk_bf, *Kmat_bf, *W2T_bf, *attn_bf;
    float* Sbuf;
    cudaGetSymbolAddress((void**)&joint_bf, g_joint_bf);
    cudaGetSymbolAddress((void**)&conf_bf,  g_conf_bf);
    cudaGetSymbolAddress((void**)&Wq_bf,    g_Wq_bf);
    cudaGetSymbolAddress((void**)&Wk_bf,    g_Wk_bf);
    cudaGetSymbolAddress((void**)&Kmat_bf,  g_Kmat_bf);
    cudaGetSymbolAddress((void**)&W2T_bf,   g_W2T_bf);
    cudaGetSymbolAddress((void**)&Sbuf,     g_S);
    cudaGetSymbolAddress((void**)&attn_bf,  g_attn_bf);

    const int smem_bytes = 2 * STAGE_BYTES + 1024;   // 33 KB
    cudaFuncSetAttribute(gemm_hmma<0, 0>, cudaFuncAttributeMaxDynamicSharedMemorySize, smem_bytes);
    cudaFuncSetAttribute(gemm_hmma<0, 1>, cudaFuncAttributeMaxDynamicSharedMemorySize, smem_bytes);
    cudaFuncSetAttribute(gemm_hmma<1, 0>, cudaFuncAttributeMaxDynamicSharedMemorySize, smem_bytes);
    cudaFuncSetAttribute(gemm_hmma<1, 2>, cudaFuncAttributeMaxDynamicSharedMemorySize, smem_bytes);

    // fused conversions
    conv_all<<<(N4_TOTAL + 255) / 256, 256>>>(joint, conf, Wq, Wk,
                                              joint_bf, conf_bf, Wq_bf, Wk_bf);
    // G1 (NN): Kmat[256,768] = conf_bf @ Wk_bf  (K=1024)
    gemm_hmma<1, 0><<<dim3(PP / TN, KK / TM), 128, smem_bytes>>>(
        conf_bf, Wk_bf, Kmat_bf, nullptr, PP, DD, 1.0f);
    // G2 (NT): W2T[256,1024] = Kmat @ Wq_bf^T  (K=768)
    gemm_hmma<0, 0><<<dim3(DD / TN, KK / TM), 128, smem_bytes>>>(
        Kmat_bf, Wq_bf, W2T_bf, nullptr, DD, PP, 1.0f);
    // G3 (NT): S[1024,256] = joint_bf @ W2T^T * (1/32)  (K=1024)
    gemm_hmma<0, 1><<<dim3(KK / TN, BB / TM), 128, smem_bytes>>>(
        joint_bf, W2T_bf, Sbuf, nullptr, KK, DD, 0.03125f);
    // softmax rows (* prior) -> attn bf16
    softmax_bf16<<<BB / 8, 256>>>(Sbuf, prior, attn_bf);
    // G4 (NN): out[1024,1024] = attn_bf @ conf_bf + joint  (K=256)
    gemm_hmma<1, 2><<<dim3(DD / TN, BB / TM), 128, smem_bytes>>>(
        attn_bf, conf_bf, out, joint, DD, KK, 1.0f);
}

// round 8
// speedup vs baseline: 6.2198x; 1.1872x over previous
#include <cuda_runtime.h>
#include <cuda_bf16.h>
#include <cstdint>

// Shapes (fixed): joint [B=1024, D=1024], conf [K=256, D=1024], prior [K,1],
// Wq [D, P=768], Wk [D, P=768], out [B, D]. All fp32 in global.
//
// Dataflow (bf16 HMMA mma.sync, fp32 accum; split-K for grid width):
//   conv:  joint_bf, conf_bf, Wq_bf, Wk_bf        (one fused kernel)
//   G1(NN, splitK=4): part = conf_bf @ Wk_bf      (K=1024) -> fp32 partials
//        reduce -> Kmat_bf [256,768]
//   G2(NT, splitK=4): part = Kmat @ Wq_bf^T       (K=768)  -> fp32 partials
//        reduce -> W2T_bf [256,1024]
//   G3(NT, splitK=4): part = joint_bf @ W2T^T     (K=1024) -> fp32 partials
//   softmax (fused: sum partials, *1/32, softmax, *prior) -> attn_bf [1024,256]
//   G4(NN): out = attn_bf @ conf_bf + joint       (K=256)  -> f32

#define BB 1024
#define KK 256
#define DD 1024
#define PP 768
#define SPLITS 4

// ---------------- scratch (device globals; no allocation allowed) ----------
__device__ __align__(16) __nv_bfloat16 g_joint_bf[BB * DD];
__device__ __align__(16) __nv_bfloat16 g_conf_bf[KK * DD];
__device__ __align__(16) __nv_bfloat16 g_Wq_bf[DD * PP];
__device__ __align__(16) __nv_bfloat16 g_Wk_bf[DD * PP];
__device__ __align__(16) __nv_bfloat16 g_Kmat_bf[KK * PP];
__device__ __align__(16) __nv_bfloat16 g_W2T_bf[KK * DD];
__device__ __align__(16) __nv_bfloat16 g_attn_bf[BB * KK];
__device__ __align__(16) float         g_part[SPLITS * BB * KK];  // 4 MB, reused

// ---------------- baseline-PTX helpers --------------------------------------
__device__ __forceinline__ uint32_t smem_u32(const void* p) {
    uint32_t a;
    asm("{ .reg .u64 t; cvta.to.shared.u64 t, %1; cvt.u32.u64 %0, t; }"
        : "=r"(a) : "l"(p));
    return a;
}
__device__ __forceinline__ void cp_async16(uint32_t dst, const void* src) {
    asm volatile("cp.async.cg.shared.global [%0], [%1], 16;"
                 :: "r"(dst), "l"(src) : "memory");
}
__device__ __forceinline__ void cp_commit() {
    asm volatile("cp.async.commit_group;" ::: "memory");
}
__device__ __forceinline__ void cp_wait1() {
    asm volatile("cp.async.wait_group 1;" ::: "memory");
}
__device__ __forceinline__ void cp_wait0() {
    asm volatile("cp.async.wait_group 0;" ::: "memory");
}
__device__ __forceinline__ void ldmatrix_x4(uint32_t* r, uint32_t addr) {
    asm volatile("ldmatrix.sync.aligned.m8n8.x4.shared.b16 {%0,%1,%2,%3}, [%4];"
                 : "=r"(r[0]), "=r"(r[1]), "=r"(r[2]), "=r"(r[3]) : "r"(addr));
}
__device__ __forceinline__ void ldmatrix_x4_trans(uint32_t* r, uint32_t addr) {
    asm volatile("ldmatrix.sync.aligned.m8n8.x4.trans.shared.b16 {%0,%1,%2,%3}, [%4];"
                 : "=r"(r[0]), "=r"(r[1]), "=r"(r[2]), "=r"(r[3]) : "r"(addr));
}
__device__ __forceinline__ void mma_bf16(float* c, const uint32_t* a,
                                         uint32_t b0, uint32_t b1) {
    asm volatile(
        "mma.sync.aligned.m16n8k16.row.col.f32.bf16.bf16.f32 "
        "{%0,%1,%2,%3}, {%4,%5,%6,%7}, {%8,%9}, {%0,%1,%2,%3};"
        : "+f"(c[0]), "+f"(c[1]), "+f"(c[2]), "+f"(c[3])
        : "r"(a[0]), "r"(a[1]), "r"(a[2]), "r"(a[3]), "r"(b0), "r"(b1));
}
__device__ __forceinline__ uint32_t sw128(uint32_t off) {
    return off ^ ((off >> 3) & 0x70);
}

// ---------------- fused fp32 -> bf16 conversion (all 4 inputs) --------------
#define N4_JOINT  (BB * DD / 4)
#define N4_CONF   (KK * DD / 4)
#define N4_W      (DD * PP / 4)
#define N4_TOTAL  (N4_JOINT + N4_CONF + 2 * N4_W)

__global__ __launch_bounds__(256) void conv_all(
    const float* __restrict__ joint, const float* __restrict__ conf,
    const float* __restrict__ wq, const float* __restrict__ wk,
    __nv_bfloat16* __restrict__ jb, __nv_bfloat16* __restrict__ cb,
    __nv_bfloat16* __restrict__ qb, __nv_bfloat16* __restrict__ kb)
{
    int i = blockIdx.x * blockDim.x + threadIdx.x;
    const float* src;
    __nv_bfloat16* dst;
    int off;
    if (i < N4_JOINT)                       { src = joint; dst = jb; off = i; }
    else if (i < N4_JOINT + N4_CONF)        { src = conf;  dst = cb; off = i - N4_JOINT; }
    else if (i < N4_JOINT + N4_CONF + N4_W) { src = wq;    dst = qb; off = i - N4_JOINT - N4_CONF; }
    else if (i < N4_TOTAL)                  { src = wk;    dst = kb; off = i - N4_JOINT - N4_CONF - N4_W; }
    else return;
    float4 v = ((const float4*)src)[off];
    __nv_bfloat162 a = __floats2bfloat162_rn(v.x, v.y);
    __nv_bfloat162 b = __floats2bfloat162_rn(v.z, v.w);
    uint2 u;
    u.x = *reinterpret_cast<uint32_t*>(&a);
    u.y = *reinterpret_cast<uint32_t*>(&b);
    ((uint2*)dst)[off] = u;
}

// ------- reduce SPLITS fp32 partials -> bf16 ---------------------------------
__global__ __launch_bounds__(256) void reduce_bf16(
    const float* __restrict__ part, __nv_bfloat16* __restrict__ out, int n4, int stride4)
{
    int i = blockIdx.x * blockDim.x + threadIdx.x;
    if (i >= n4) return;
    float4 s = ((const float4*)part)[i];
    #pragma unroll
    for (int sp = 1; sp < SPLITS; ++sp) {
        float4 v = ((const float4*)part)[i + sp * stride4];
        s.x += v.x; s.y += v.y; s.z += v.z; s.w += v.w;
    }
    __nv_bfloat162 a = __floats2bfloat162_rn(s.x, s.y);
    __nv_bfloat162 b = __floats2bfloat162_rn(s.z, s.w);
    uint2 u;
    u.x = *reinterpret_cast<uint32_t*>(&a);
    u.y = *reinterpret_cast<uint32_t*>(&b);
    ((uint2*)out)[i] = u;
}

// ------- softmax: sum 4 S-partials, *1/32, softmax, *prior -> bf16 -----------
__global__ __launch_bounds__(256) void softmax_bf16(
    const float* __restrict__ Sp, const float* __restrict__ prior,
    __nv_bfloat16* __restrict__ A)
{
    const int STR4 = BB * KK / 4;   // float4 stride between splits
    int w = threadIdx.x >> 5, lid = threadIdx.x & 31;
    int row = blockIdx.x * 8 + w;
    int base4 = row * (KK / 4);
    float4 v0 = ((const float4*)Sp)[base4 + lid];
    float4 v1 = ((const float4*)Sp)[base4 + lid + 32];
    #pragma unroll
    for (int sp = 1; sp < SPLITS; ++sp) {
        float4 a = ((const float4*)Sp)[base4 + lid + sp * STR4];
        float4 b = ((const float4*)Sp)[base4 + lid + 32 + sp * STR4];
        v0.x += a.x; v0.y += a.y; v0.z += a.z; v0.w += a.w;
        v1.x += b.x; v1.y += b.y; v1.z += b.z; v1.w += b.w;
    }
    const float alpha = 0.03125f;
    float e[8] = {v0.x * alpha, v0.y * alpha, v0.z * alpha, v0.w * alpha,
                  v1.x * alpha, v1.y * alpha, v1.z * alpha, v1.w * alpha};
    float mx = e[0];
    #pragma unroll
    for (int i = 1; i < 8; i++) mx = fmaxf(mx, e[i]);
    #pragma unroll
    for (int o = 16; o; o >>= 1) mx = fmaxf(mx, __shfl_xor_sync(~0u, mx, o));
    float s = 0.f;
    #pragma unroll
    for (int i = 0; i < 8; i++) { e[i] = __expf(e[i] - mx); s += e[i]; }
    #pragma unroll
    for (int o = 16; o; o >>= 1) s += __shfl_xor_sync(~0u, s, o);
    float inv = 1.0f / s;
    float4 p0 = ((const float4*)prior)[lid];
    float4 p1 = ((const float4*)prior)[lid + 32];
    __nv_bfloat162 b01 = __floats2bfloat162_rn(e[0] * inv * p0.x, e[1] * inv * p0.y);
    __nv_bfloat162 b23 = __floats2bfloat162_rn(e[2] * inv * p0.z, e[3] * inv * p0.w);
    __nv_bfloat162 b45 = __floats2bfloat162_rn(e[4] * inv * p1.x, e[5] * inv * p1.y);
    __nv_bfloat162 b67 = __floats2bfloat162_rn(e[6] * inv * p1.z, e[7] * inv * p1.w);
    uint2 lo = make_uint2(*reinterpret_cast<uint32_t*>(&b01), *reinterpret_cast<uint32_t*>(&b23));
    uint2 hi = make_uint2(*reinterpret_cast<uint32_t*>(&b45), *reinterpret_cast<uint32_t*>(&b67));
    *(uint2*)(A + (size_t)row * KK + lid * 4)       = lo;
    *(uint2*)(A + (size_t)row * KK + 128 + lid * 4) = hi;
}

// ---------------- HMMA GEMM core (64x64 tile, 4 warps, BK=64) ---------------
#define TM 64
#define TN 64
#define TKB 128
#define A_BYTES (TM * TKB)
#define STAGE_BYTES (2 * A_BYTES)

// Shared mainloop. SPLIT: partition K by blockIdx.z (Kc per split); writes fp32
// partials to Cout + z*M*N. Non-split: MODE 2 = f32 out + resid (G4).
template <int BNN, int SPLIT, int MODE>
__global__ __launch_bounds__(128) void gemm_hmma(
    const __nv_bfloat16* __restrict__ A, const __nv_bfloat16* __restrict__ B,
    void* __restrict__ Cout, const float* __restrict__ resid,
    int Ntot, int Mtot, int K, int Kc)
{
    extern __shared__ char dsm_raw[];
    char* dsm = (char*)(((uintptr_t)dsm_raw + 1023) & ~(uintptr_t)1023);
    const uint32_t smem_base = smem_u32(dsm);

    const int tid = threadIdx.x;
    const int wid = tid >> 5;
    const int lid = tid & 31;
    const int wm = (wid >> 1) * 32;
    const int wn = (wid & 1) * 32;

    const int row0 = blockIdx.y * TM;
    const int col0 = blockIdx.x * TN;
    const int Koff = SPLIT ? blockIdx.z * Kc : 0;
    const int nk = (SPLIT ? Kc : K) >> 6;

    const char* Abase = (const char*)A;
    const char* Bbase = (const char*)B;

    float acc[2][4][4] = {};

    auto load_stage = [&](int s, int it) {
        const uint32_t sA = smem_base + s * STAGE_BYTES;
        const uint32_t sB = sA + A_BYTES;
        #pragma unroll
        for (int i = 0; i < 4; i++) {
            int ci = tid + i * 128;
            int r = ci >> 3, c16 = ci & 7;
            size_t gb = ((size_t)(row0 + r) * K + Koff + it * 64) * 2 + c16 * 16;
            uint32_t off = r * TKB + c16 * 16;
            cp_async16(sA + sw128(off), Abase + gb);
        }
        #pragma unroll
        for (int i = 0; i < 4; i++) {
            int ci = tid + i * 128;
            int r = ci >> 3, c16 = ci & 7;
            size_t gb;
            if (BNN)
                gb = ((size_t)(Koff + it * 64 + r) * Ntot + col0) * 2 + c16 * 16;
            else
                gb = ((size_t)(col0 + r) * K + Koff + it * 64) * 2 + c16 * 16;
            uint32_t off = r * TKB + c16 * 16;
            cp_async16(sB + sw128(off), Bbase + gb);
        }
        cp_commit();
    };

    load_stage(0, 0);

    for (int it = 0; it < nk; ++it) {
        if (it + 1 < nk) { load_stage((it + 1) & 1, it + 1); cp_wait1(); }
        else             { cp_wait0(); }
        __syncthreads();

        const uint32_t sA = smem_base + (it & 1) * STAGE_BYTES;
        const uint32_t sB = sA + A_BYTES;

        #pragma unroll
        for (int ks = 0; ks < 4; ++ks) {
            uint32_t afr[2][4], bfr[2][4];
            #pragma unroll
            for (int mi = 0; mi < 2; ++mi) {
                int row = wm + mi * 16 + (lid & 15);
                uint32_t off = row * TKB + ks * 32 + (lid >> 4) * 16;
                ldmatrix_x4(afr[mi], sA + sw128(off));
            }
            #pragma unroll
            for (int np = 0; np < 2; ++np) {
                if (BNN) {
                    int k = ks * 16 + ((lid >> 3) & 1) * 8 + (lid & 7);
                    int n = wn + np * 16 + (lid >> 4) * 8;
                    uint32_t off = k * TKB + n * 2;
                    ldmatrix_x4_trans(bfr[np], sB + sw128(off));
                } else {
                    int row = wn + np * 16 + ((lid >> 4) << 3) + (lid & 7);
                    uint32_t off = row * TKB + ks * 32 + ((lid >> 3) & 1) * 16;
                    ldmatrix_x4(bfr[np], sB + sw128(off));
                }
            }
            #pragma unroll
            for (int mi = 0; mi < 2; ++mi)
                #pragma unroll
                for (int ni = 0; ni < 4; ++ni)
                    mma_bf16(acc[mi][ni], afr[mi],
                             bfr[ni >> 1][(ni & 1) * 2],
                             bfr[ni >> 1][(ni & 1) * 2 + 1]);
        }
        __syncthreads();
    }

    const int group = lid >> 2;
    const int tc = (lid & 3) * 2;
    float* opart = (float*)Cout + (SPLIT ? (size_t)blockIdx.z * Mtot * Ntot : 0);
    #pragma unroll
    for (int mi = 0; mi < 2; ++mi) {
        #pragma unroll
        for (int ni = 0; ni < 4; ++ni) {
            int r = row0 + wm + mi * 16 + group;
            int c = col0 + wn + ni * 8 + tc;
            float* cc = acc[mi][ni];
            if (SPLIT) {
                *(float2*)(opart + (size_t)r * Ntot + c) = make_float2(cc[0], cc[1]);
                *(float2*)(opart + (size_t)(r + 8) * Ntot + c) = make_float2(cc[2], cc[3]);
            } else if (MODE == 2) {
                float* o = (float*)Cout;
                float2 j0 = *(const float2*)(resid + (size_t)r * Ntot + c);
                float2 j1 = *(const float2*)(resid + (size_t)(r + 8) * Ntot + c);
                *(float2*)(o + (size_t)r * Ntot + c) = make_float2(cc[0] + j0.x, cc[1] + j0.y);
                *(float2*)(o + (size_t)(r + 8) * Ntot + c) = make_float2(cc[2] + j1.x, cc[3] + j1.y);
            }
        }
    }
}

// ---------------- host ------------------------------------------------------
extern "C" void kernel_launch(void* const* d_in, const int* in_sizes, int n_in,
                              void* d_out, int out_size)
{
    const float* joint = (const float*)d_in[0];
    const float* conf  = (const float*)d_in[1];
    const float* prior = (const float*)d_in[2];
    const float* Wq    = (const float*)d_in[3];
    const float* Wk    = (const float*)d_in[4];
    float* out = (float*)d_out;

    __nv_bfloat16 *joint_bf, *conf_bf, *Wq_bf, *Wk_bf, *Kmat_bf, *W2T_bf, *attn_bf;
    float* part;
    cudaGetSymbolAddress((void**)&joint_bf, g_joint_bf);
    cudaGetSymbolAddress((void**)&conf_bf,  g_conf_bf);
    cudaGetSymbolAddress((void**)&Wq_bf,    g_Wq_bf);
    cudaGetSymbolAddress((void**)&Wk_bf,    g_Wk_bf);
    cudaGetSymbolAddress((void**)&Kmat_bf,  g_Kmat_bf);
    cudaGetSymbolAddress((void**)&W2T_bf,   g_W2T_bf);
    cudaGetSymbolAddress((void**)&attn_bf,  g_attn_bf);
    cudaGetSymbolAddress((void**)&part,     g_part);

    const int smem_bytes = 2 * STAGE_BYTES + 1024;   // 33 KB
    cudaFuncSetAttribute((const void*)gemm_hmma<1, 1, 0>, cudaFuncAttributeMaxDynamicSharedMemorySize, smem_bytes);
    cudaFuncSetAttribute((const void*)gemm_hmma<0, 1, 0>, cudaFuncAttributeMaxDynamicSharedMemorySize, smem_bytes);
    cudaFuncSetAttribute((const void*)gemm_hmma<1, 0, 2>, cudaFuncAttributeMaxDynamicSharedMemorySize, smem_bytes);

    // fused conversions
    conv_all<<<(N4_TOTAL + 255) / 256, 256>>>(joint, conf, Wq, Wk,
                                              joint_bf, conf_bf, Wq_bf, Wk_bf);
    // G1 (NN, split-K 4): part = conf_bf @ Wk_bf  (K=1024, Kc=256) -> 192 CTAs
    gemm_hmma<1, 1, 0><<<dim3(PP / TN, KK / TM, SPLITS), 128, smem_bytes>>>(
        conf_bf, Wk_bf, part, nullptr, PP, KK, DD, DD / SPLITS);
    reduce_bf16<<<(KK * PP / 4 + 255) / 256, 256>>>(part, Kmat_bf, KK * PP / 4, KK * PP / 4);
    // G2 (NT, split-K 4): part = Kmat @ Wq_bf^T  (K=768, Kc=192) -> 256 CTAs
    gemm_hmma<0, 1, 0><<<dim3(DD / TN, KK / TM, SPLITS), 128, smem_bytes>>>(
        Kmat_bf, Wq_bf, part, nullptr, DD, KK, PP, PP / SPLITS);
    reduce_bf16<<<(KK * DD / 4 + 255) / 256, 256>>>(part, W2T_bf, KK * DD / 4, KK * DD / 4);
    // G3 (NT, split-K 4): part = joint_bf @ W2T^T  (K=1024, Kc=256) -> 256 CTAs
    gemm_hmma<0, 1, 0><<<dim3(KK / TN, BB / TM, SPLITS), 128, smem_bytes>>>(
        joint_bf, W2T_bf, part, nullptr, KK, BB, DD, DD / SPLITS);
    // softmax: fused 4-way partial reduce + *1/32 + softmax + *prior -> attn
    softmax_bf16<<<BB / 8, 256>>>(part, prior, attn_bf);
    // G4 (NN): out = attn_bf @ conf_bf + joint  (K=256) -> 256 CTAs
    gemm_hmma<1, 0, 2><<<dim3(DD / TN, BB / TM, 1), 128, smem_bytes>>>(
        attn_bf, conf_bf, out, joint, DD, BB, KK, KK);
}